// round 1
// baseline (speedup 1.0000x reference)
#include <cuda_runtime.h>
#include <math.h>

#define S_LEN   4096
#define DMODEL  1024
#define NHEADS  16
#define DK      64

// Scratch (allocation-free: __device__ globals)
__device__ float g_q[S_LEN * DMODEL];
__device__ float g_k[S_LEN * DMODEL];
__device__ float g_v[S_LEN * DMODEL];
__device__ float g_attn[S_LEN * DMODEL];

// ---------------------------------------------------------------------------
// SGEMM: C[M,N] = A[M,K] @ W[N,K]^T + bias[N]
// BM=BN=128, BK=8, 256 threads, 8x8 register micro-tile per thread.
// ---------------------------------------------------------------------------
__global__ __launch_bounds__(256) void sgemm_bias_kernel(
    const float* __restrict__ A, const float* __restrict__ W,
    const float* __restrict__ bias, float* __restrict__ C,
    int M, int N, int K)
{
    const int BM = 128, BN = 128, BK = 8;
    __shared__ float As[BK][BM];
    __shared__ float Ws[BK][BN];

    int tid = threadIdx.x;
    int m0 = blockIdx.y * BM;
    int n0 = blockIdx.x * BN;
    int tx = tid & 15;        // 0..15  (N direction)
    int ty = tid >> 4;        // 0..15  (M direction)

    int lr = tid >> 1;        // 0..127 load row
    int lc = (tid & 1) * 4;   // 0 or 4 load col (k)

    const float* Aptr = A + (size_t)(m0 + lr) * K + lc;
    const float* Wptr = W + (size_t)(n0 + lr) * K + lc;

    float acc[8][8] = {};

    for (int k0 = 0; k0 < K; k0 += BK) {
        float4 a4 = *(const float4*)(Aptr + k0);
        float4 w4 = *(const float4*)(Wptr + k0);
        As[lc + 0][lr] = a4.x; As[lc + 1][lr] = a4.y;
        As[lc + 2][lr] = a4.z; As[lc + 3][lr] = a4.w;
        Ws[lc + 0][lr] = w4.x; Ws[lc + 1][lr] = w4.y;
        Ws[lc + 2][lr] = w4.z; Ws[lc + 3][lr] = w4.w;
        __syncthreads();

        #pragma unroll
        for (int k = 0; k < BK; k++) {
            float a[8], b[8];
            *(float4*)(a + 0) = *(const float4*)(&As[k][ty * 8 + 0]);
            *(float4*)(a + 4) = *(const float4*)(&As[k][ty * 8 + 4]);
            *(float4*)(b + 0) = *(const float4*)(&Ws[k][tx * 8 + 0]);
            *(float4*)(b + 4) = *(const float4*)(&Ws[k][tx * 8 + 4]);
            #pragma unroll
            for (int i = 0; i < 8; i++)
                #pragma unroll
                for (int j = 0; j < 8; j++)
                    acc[i][j] += a[i] * b[j];
        }
        __syncthreads();
    }

    // Epilogue: add bias, store
    float b8[8];
    *(float4*)(b8 + 0) = *(const float4*)(bias + n0 + tx * 8 + 0);
    *(float4*)(b8 + 4) = *(const float4*)(bias + n0 + tx * 8 + 4);
    #pragma unroll
    for (int i = 0; i < 8; i++) {
        int m = m0 + ty * 8 + i;
        float4 o0 = make_float4(acc[i][0] + b8[0], acc[i][1] + b8[1],
                                acc[i][2] + b8[2], acc[i][3] + b8[3]);
        float4 o1 = make_float4(acc[i][4] + b8[4], acc[i][5] + b8[5],
                                acc[i][6] + b8[6], acc[i][7] + b8[7]);
        *(float4*)(C + (size_t)m * N + n0 + tx * 8 + 0) = o0;
        *(float4*)(C + (size_t)m * N + n0 + tx * 8 + 4) = o1;
    }
}

// ---------------------------------------------------------------------------
// Flash-style causal attention, fp32.
// Grid: (S/64, NHEADS). Block: 256 threads.
// Each block: 64 query rows of one head; iterates over key tiles of 64.
// Thread (tx,ty): owns S rows ty*4..+3 (queries), and output cols tx*4..+3.
// ---------------------------------------------------------------------------
#define BQ   64
#define BKV  64
#define PAD  68   // floats per smem row (bank-conflict padding, 16B aligned)

__global__ __launch_bounds__(256) void attn_kernel(
    const float* __restrict__ Q, const float* __restrict__ K,
    const float* __restrict__ V, float* __restrict__ O)
{
    extern __shared__ float smem[];
    float* Qs  = smem;                 // [64][PAD]   Qs[row][d]
    float* KsT = smem + 64 * PAD;      // [64][PAD]   KsT[d][key]
    float* Vs  = smem + 2 * 64 * PAD;  // [64][PAD]   Vs[key][d]
    float* Ps  = smem + 3 * 64 * PAD;  // [64][PAD]   Ps[row][key]

    int tid = threadIdx.x;
    int tx = tid & 15;   // 0..15
    int ty = tid >> 4;   // 0..15
    int h  = blockIdx.y;
    int qb = blockIdx.x;
    int q0 = qb * BQ;
    int col0 = h * DK;
    const float scale = 0.125f;  // 1/sqrt(64)

    // Load Q tile [64 x 64]
    #pragma unroll
    for (int i = 0; i < 4; i++) {
        int lin = tid + i * 256;       // 0..1023
        int row = lin >> 4;
        int c4  = (lin & 15) * 4;
        float4 qv = *(const float4*)(Q + (size_t)(q0 + row) * DMODEL + col0 + c4);
        *(float4*)(Qs + row * PAD + c4) = qv;
    }

    float acc[4][4] = {};
    float m_i[4], l_i[4];
    #pragma unroll
    for (int r = 0; r < 4; r++) { m_i[r] = -1e30f; l_i[r] = 0.0f; }

    for (int kt = 0; kt <= qb; kt++) {
        int k0 = kt * BKV;
        __syncthreads();   // previous iteration's Ps/Vs reads done
        // Load K (transposed into smem) and V tiles
        #pragma unroll
        for (int i = 0; i < 4; i++) {
            int lin = tid + i * 256;
            int row = lin >> 4;
            int c4  = (lin & 15) * 4;
            float4 kv = *(const float4*)(K + (size_t)(k0 + row) * DMODEL + col0 + c4);
            KsT[(c4 + 0) * PAD + row] = kv.x;
            KsT[(c4 + 1) * PAD + row] = kv.y;
            KsT[(c4 + 2) * PAD + row] = kv.z;
            KsT[(c4 + 3) * PAD + row] = kv.w;
            float4 vv = *(const float4*)(V + (size_t)(k0 + row) * DMODEL + col0 + c4);
            *(float4*)(Vs + row * PAD + c4) = vv;
        }
        __syncthreads();

        // S = Q @ K^T for this tile: s[r][c], query rows ty*4+r, keys tx*4+c
        float s_[4][4] = {};
        #pragma unroll 4
        for (int d = 0; d < DK; d += 4) {
            float qrow[4][4];
            #pragma unroll
            for (int r = 0; r < 4; r++)
                *(float4*)qrow[r] = *(const float4*)(Qs + (ty * 4 + r) * PAD + d);
            #pragma unroll
            for (int dd = 0; dd < 4; dd++) {
                float4 k4 = *(const float4*)(KsT + (d + dd) * PAD + tx * 4);
                #pragma unroll
                for (int r = 0; r < 4; r++) {
                    s_[r][0] += qrow[r][dd] * k4.x;
                    s_[r][1] += qrow[r][dd] * k4.y;
                    s_[r][2] += qrow[r][dd] * k4.z;
                    s_[r][3] += qrow[r][dd] * k4.w;
                }
            }
        }

        // Scale + causal mask (only the diagonal tile needs masking)
        bool diag = (kt == qb);
        #pragma unroll
        for (int r = 0; r < 4; r++)
            #pragma unroll
            for (int c = 0; c < 4; c++) {
                float v = s_[r][c] * scale;
                if (diag && (tx * 4 + c) > (ty * 4 + r)) v = -1e30f;
                s_[r][c] = v;
            }

        // Online softmax: row reductions over the 16-thread tx-group (shfl)
        #pragma unroll
        for (int r = 0; r < 4; r++) {
            float mx = fmaxf(fmaxf(s_[r][0], s_[r][1]), fmaxf(s_[r][2], s_[r][3]));
            #pragma unroll
            for (int o = 8; o >= 1; o >>= 1)
                mx = fmaxf(mx, __shfl_xor_sync(0xffffffffu, mx, o));
            float m_new = fmaxf(m_i[r], mx);
            float alpha = __expf(m_i[r] - m_new);
            float p0 = __expf(s_[r][0] - m_new);
            float p1 = __expf(s_[r][1] - m_new);
            float p2 = __expf(s_[r][2] - m_new);
            float p3 = __expf(s_[r][3] - m_new);
            *(float4*)(Ps + (ty * 4 + r) * PAD + tx * 4) = make_float4(p0, p1, p2, p3);
            float sum = p0 + p1 + p2 + p3;
            #pragma unroll
            for (int o = 8; o >= 1; o >>= 1)
                sum += __shfl_xor_sync(0xffffffffu, sum, o);
            l_i[r] = l_i[r] * alpha + sum;
            m_i[r] = m_new;
            #pragma unroll
            for (int c = 0; c < 4; c++) acc[r][c] *= alpha;
        }
        __syncthreads();  // Ps fully written

        // O += P @ V : acc[r][c] over keys kk
        #pragma unroll 4
        for (int kk = 0; kk < BKV; kk += 4) {
            float prow[4][4];
            #pragma unroll
            for (int r = 0; r < 4; r++)
                *(float4*)prow[r] = *(const float4*)(Ps + (ty * 4 + r) * PAD + kk);
            #pragma unroll
            for (int j = 0; j < 4; j++) {
                float4 v4 = *(const float4*)(Vs + (kk + j) * PAD + tx * 4);
                #pragma unroll
                for (int r = 0; r < 4; r++) {
                    acc[r][0] += prow[r][j] * v4.x;
                    acc[r][1] += prow[r][j] * v4.y;
                    acc[r][2] += prow[r][j] * v4.z;
                    acc[r][3] += prow[r][j] * v4.w;
                }
            }
        }
    }

    // Epilogue: normalize and store [S, DMODEL] layout (head h -> cols h*64..)
    #pragma unroll
    for (int r = 0; r < 4; r++) {
        float inv = 1.0f / l_i[r];
        float4 o = make_float4(acc[r][0] * inv, acc[r][1] * inv,
                               acc[r][2] * inv, acc[r][3] * inv);
        *(float4*)(O + (size_t)(q0 + ty * 4 + r) * DMODEL + col0 + tx * 4) = o;
    }
}

// ---------------------------------------------------------------------------
extern "C" void kernel_launch(void* const* d_in, const int* in_sizes, int n_in,
                              void* d_out, int out_size)
{
    const float* x  = (const float*)d_in[0];
    const float* Wq = (const float*)d_in[1];
    const float* bq = (const float*)d_in[2];
    const float* Wk = (const float*)d_in[3];
    const float* bk = (const float*)d_in[4];
    const float* Wv = (const float*)d_in[5];
    const float* bv = (const float*)d_in[6];
    const float* Wo = (const float*)d_in[7];
    const float* bo = (const float*)d_in[8];
    float* out = (float*)d_out;

    float *q, *k, *v, *attn;
    cudaGetSymbolAddress((void**)&q,    g_q);
    cudaGetSymbolAddress((void**)&k,    g_k);
    cudaGetSymbolAddress((void**)&v,    g_v);
    cudaGetSymbolAddress((void**)&attn, g_attn);

    const int SMEM_ATTN = 4 * 64 * PAD * sizeof(float);  // 69632 bytes
    cudaFuncSetAttribute(attn_kernel,
                         cudaFuncAttributeMaxDynamicSharedMemorySize, SMEM_ATTN);

    dim3 gthreads(256);
    dim3 ggrid(DMODEL / 128, S_LEN / 128);

    sgemm_bias_kernel<<<ggrid, gthreads>>>(x, Wq, bq, q, S_LEN, DMODEL, DMODEL);
    sgemm_bias_kernel<<<ggrid, gthreads>>>(x, Wk, bk, k, S_LEN, DMODEL, DMODEL);
    sgemm_bias_kernel<<<ggrid, gthreads>>>(x, Wv, bv, v, S_LEN, DMODEL, DMODEL);

    attn_kernel<<<dim3(S_LEN / BQ, NHEADS), 256, SMEM_ATTN>>>(q, k, v, attn);

    sgemm_bias_kernel<<<ggrid, gthreads>>>(attn, Wo, bo, out, S_LEN, DMODEL, DMODEL);
}

// round 7
// speedup vs baseline: 1.3423x; 1.3423x over previous
#include <cuda_runtime.h>
#include <cuda_bf16.h>
#include <cstdint>
#include <math.h>

#define S_LEN   4096
#define DMODEL  1024
#define NHEADS  16
#define DK      64

// ---------------- scratch (__device__ globals: allocation-free) ------------
__device__ float g_q[S_LEN * DMODEL];
__device__ float g_k[S_LEN * DMODEL];
__device__ float g_v[S_LEN * DMODEL];
__device__ float g_attn[S_LEN * DMODEL];

__device__ __nv_bfloat16 g_xhi[S_LEN * DMODEL];   // also reused for attn hi
__device__ __nv_bfloat16 g_xlo[S_LEN * DMODEL];   // also reused for attn lo
__device__ __nv_bfloat16 g_wqhi[DMODEL * DMODEL];
__device__ __nv_bfloat16 g_wqlo[DMODEL * DMODEL];
__device__ __nv_bfloat16 g_wkhi[DMODEL * DMODEL];
__device__ __nv_bfloat16 g_wklo[DMODEL * DMODEL];
__device__ __nv_bfloat16 g_wvhi[DMODEL * DMODEL];
__device__ __nv_bfloat16 g_wvlo[DMODEL * DMODEL];
__device__ __nv_bfloat16 g_wohi[DMODEL * DMODEL];
__device__ __nv_bfloat16 g_wolo[DMODEL * DMODEL];

// ---------------------------------------------------------------------------
// fp32 -> bf16 hi/lo split (elementwise), float4 vectorized
// ---------------------------------------------------------------------------
__global__ __launch_bounds__(256) void cvt_split_kernel(
    const float* __restrict__ src,
    __nv_bfloat16* __restrict__ hi, __nv_bfloat16* __restrict__ lo, int n4)
{
    int i = blockIdx.x * 256 + threadIdx.x;
    if (i >= n4) return;
    float4 v = ((const float4*)src)[i];
    __nv_bfloat16 h0 = __float2bfloat16(v.x);
    __nv_bfloat16 h1 = __float2bfloat16(v.y);
    __nv_bfloat16 h2 = __float2bfloat16(v.z);
    __nv_bfloat16 h3 = __float2bfloat16(v.w);
    __nv_bfloat16 l0 = __float2bfloat16(v.x - __bfloat162float(h0));
    __nv_bfloat16 l1 = __float2bfloat16(v.y - __bfloat162float(h1));
    __nv_bfloat16 l2 = __float2bfloat16(v.z - __bfloat162float(h2));
    __nv_bfloat16 l3 = __float2bfloat16(v.w - __bfloat162float(h3));
    ((__nv_bfloat162*)hi)[2 * i + 0] = __nv_bfloat162(h0, h1);
    ((__nv_bfloat162*)hi)[2 * i + 1] = __nv_bfloat162(h2, h3);
    ((__nv_bfloat162*)lo)[2 * i + 0] = __nv_bfloat162(l0, l1);
    ((__nv_bfloat162*)lo)[2 * i + 1] = __nv_bfloat162(l2, l3);
}

// ---------------------------------------------------------------------------
// HMMA helpers (sm_80-era PTX — compiles at plain sm_103 target)
// ---------------------------------------------------------------------------
__device__ __forceinline__ uint32_t lds32(uint32_t addr) {
    uint32_t v;
    asm volatile("ld.shared.b32 %0, [%1];" : "=r"(v) : "r"(addr));
    return v;
}

__device__ __forceinline__ void mma16816(float* c, const uint32_t* a,
                                         uint32_t b0, uint32_t b1) {
    asm volatile(
        "mma.sync.aligned.m16n8k16.row.col.f32.bf16.bf16.f32 "
        "{%0,%1,%2,%3}, {%4,%5,%6,%7}, {%8,%9}, {%0,%1,%2,%3};\n"
        : "+f"(c[0]), "+f"(c[1]), "+f"(c[2]), "+f"(c[3])
        : "r"(a[0]), "r"(a[1]), "r"(a[2]), "r"(a[3]), "r"(b0), "r"(b1));
}

// ---------------------------------------------------------------------------
// bf16-split tensor-core GEMM: C[M,N] = (Ahi+Alo) @ (Bhi+Blo)^T + bias
// A[M,K], B[N,K] row-major bf16. CTA 128x128, BK=32, 8 warps (32x64 each).
// cp.async double-buffered. 3-pass split: hi*hi + hi*lo + lo*hi.
// ---------------------------------------------------------------------------
#define GBK      32
#define ROW_B    80        // padded smem row stride in bytes (32 bf16 + 8 pad)
#define TILE_B   (128 * ROW_B)      // 10240
#define STAGE_B  (4 * TILE_B)       // 40960
#define GEMM_SMEM (2 * STAGE_B)     // 81920

__global__ __launch_bounds__(256) void gemm_mma_kernel(
    const __nv_bfloat16* __restrict__ Ahi, const __nv_bfloat16* __restrict__ Alo,
    const __nv_bfloat16* __restrict__ Bhi, const __nv_bfloat16* __restrict__ Blo,
    const float* __restrict__ bias, float* __restrict__ C, int K)
{
    extern __shared__ char sm_raw[];
    int tid  = threadIdx.x;
    int lane = tid & 31, wid = tid >> 5;
    int g = lane >> 2;        // 0..7
    int q = lane & 3;         // 0..3
    int warpM = (wid & 3) * 32;
    int warpN = (wid >> 2) * 64;
    int n0 = blockIdx.x * 128;
    int m0 = blockIdx.y * 128;

    uint32_t sbase = (uint32_t)__cvta_generic_to_shared(sm_raw);

    float acc[2][8][4] = {};

    const __nv_bfloat16* srcs[4] = {Ahi, Alo, Bhi, Blo};

    // --- async tile loader: 4 tiles of [128][32] bf16, 16B chunks ---
    auto issue_loads = [&](int stage, int k0) {
        uint32_t st = sbase + stage * STAGE_B;
        int row4 = tid >> 2;      // 0..63
        int ch   = tid & 3;       // 16B chunk index
        #pragma unroll
        for (int t = 0; t < 4; t++) {
            int rbase = (t < 2) ? m0 : n0;
            #pragma unroll
            for (int h = 0; h < 2; h++) {
                int row = row4 + h * 64;
                const void* gp = srcs[t] + (size_t)(rbase + row) * K + k0 + ch * 8;
                uint32_t dp = st + t * TILE_B + row * ROW_B + ch * 16;
                asm volatile("cp.async.cg.shared.global [%0], [%1], 16;\n"
                             :: "r"(dp), "l"(gp));
            }
        }
        asm volatile("cp.async.commit_group;\n" ::: "memory");
    };

    auto compute = [&](int stage) {
        uint32_t st   = sbase + stage * STAGE_B;
        uint32_t sAhi = st;
        uint32_t sAlo = st + TILE_B;
        uint32_t sBhi = st + 2 * TILE_B;
        uint32_t sBlo = st + 3 * TILE_B;
        #pragma unroll
        for (int ks = 0; ks < GBK; ks += 16) {
            int kb = ks + q * 2;
            uint32_t ahi[2][4], alo[2][4];
            #pragma unroll
            for (int i = 0; i < 2; i++) {
                int r = warpM + i * 16 + g;
                ahi[i][0] = lds32(sAhi + r * ROW_B + kb * 2);
                ahi[i][1] = lds32(sAhi + (r + 8) * ROW_B + kb * 2);
                ahi[i][2] = lds32(sAhi + r * ROW_B + (kb + 8) * 2);
                ahi[i][3] = lds32(sAhi + (r + 8) * ROW_B + (kb + 8) * 2);
                alo[i][0] = lds32(sAlo + r * ROW_B + kb * 2);
                alo[i][1] = lds32(sAlo + (r + 8) * ROW_B + kb * 2);
                alo[i][2] = lds32(sAlo + r * ROW_B + (kb + 8) * 2);
                alo[i][3] = lds32(sAlo + (r + 8) * ROW_B + (kb + 8) * 2);
            }
            #pragma unroll
            for (int j = 0; j < 8; j++) {
                int n = warpN + j * 8 + g;
                uint32_t bh0 = lds32(sBhi + n * ROW_B + kb * 2);
                uint32_t bh1 = lds32(sBhi + n * ROW_B + (kb + 8) * 2);
                uint32_t bl0 = lds32(sBlo + n * ROW_B + kb * 2);
                uint32_t bl1 = lds32(sBlo + n * ROW_B + (kb + 8) * 2);
                #pragma unroll
                for (int i = 0; i < 2; i++) {
                    mma16816(acc[i][j], ahi[i], bh0, bh1);
                    mma16816(acc[i][j], ahi[i], bl0, bl1);
                    mma16816(acc[i][j], alo[i], bh0, bh1);
                }
            }
        }
    };

    const int NITER = K / GBK;   // 32
    issue_loads(0, 0);
    for (int it = 0; it < NITER; it++) {
        if (it + 1 < NITER) {
            issue_loads((it + 1) & 1, (it + 1) * GBK);
            asm volatile("cp.async.wait_group 1;\n" ::: "memory");
        } else {
            asm volatile("cp.async.wait_group 0;\n" ::: "memory");
        }
        __syncthreads();
        compute(it & 1);
        __syncthreads();
    }

    // --- epilogue: bias add + store (float2 per c-reg pair) ---
    #pragma unroll
    for (int i = 0; i < 2; i++) {
        int r0 = m0 + warpM + i * 16 + g;
        #pragma unroll
        for (int j = 0; j < 8; j++) {
            int c = n0 + warpN + j * 8 + q * 2;
            float2 b2 = *(const float2*)(bias + c);
            float2 o0 = make_float2(acc[i][j][0] + b2.x, acc[i][j][1] + b2.y);
            float2 o1 = make_float2(acc[i][j][2] + b2.x, acc[i][j][3] + b2.y);
            *(float2*)(C + (size_t)r0 * DMODEL + c) = o0;
            *(float2*)(C + (size_t)(r0 + 8) * DMODEL + c) = o1;
        }
    }
}

// ---------------------------------------------------------------------------
// Flash-style causal attention, fp32 (unchanged — known correct)
// ---------------------------------------------------------------------------
#define BQ   64
#define BKV  64
#define PAD  68

__global__ __launch_bounds__(256) void attn_kernel(
    const float* __restrict__ Q, const float* __restrict__ K,
    const float* __restrict__ V, float* __restrict__ O)
{
    extern __shared__ float smem[];
    float* Qs  = smem;
    float* KsT = smem + 64 * PAD;
    float* Vs  = smem + 2 * 64 * PAD;
    float* Ps  = smem + 3 * 64 * PAD;

    int tid = threadIdx.x;
    int tx = tid & 15;
    int ty = tid >> 4;
    int h  = blockIdx.y;
    int qb = blockIdx.x;
    int q0 = qb * BQ;
    int col0 = h * DK;
    const float scale = 0.125f;

    #pragma unroll
    for (int i = 0; i < 4; i++) {
        int lin = tid + i * 256;
        int row = lin >> 4;
        int c4  = (lin & 15) * 4;
        float4 qv = *(const float4*)(Q + (size_t)(q0 + row) * DMODEL + col0 + c4);
        *(float4*)(Qs + row * PAD + c4) = qv;
    }

    float acc[4][4] = {};
    float m_i[4], l_i[4];
    #pragma unroll
    for (int r = 0; r < 4; r++) { m_i[r] = -1e30f; l_i[r] = 0.0f; }

    for (int kt = 0; kt <= qb; kt++) {
        int k0 = kt * BKV;
        __syncthreads();
        #pragma unroll
        for (int i = 0; i < 4; i++) {
            int lin = tid + i * 256;
            int row = lin >> 4;
            int c4  = (lin & 15) * 4;
            float4 kv = *(const float4*)(K + (size_t)(k0 + row) * DMODEL + col0 + c4);
            KsT[(c4 + 0) * PAD + row] = kv.x;
            KsT[(c4 + 1) * PAD + row] = kv.y;
            KsT[(c4 + 2) * PAD + row] = kv.z;
            KsT[(c4 + 3) * PAD + row] = kv.w;
            float4 vv = *(const float4*)(V + (size_t)(k0 + row) * DMODEL + col0 + c4);
            *(float4*)(Vs + row * PAD + c4) = vv;
        }
        __syncthreads();

        float s_[4][4] = {};
        #pragma unroll 4
        for (int d = 0; d < DK; d += 4) {
            float qrow[4][4];
            #pragma unroll
            for (int r = 0; r < 4; r++)
                *(float4*)qrow[r] = *(const float4*)(Qs + (ty * 4 + r) * PAD + d);
            #pragma unroll
            for (int dd = 0; dd < 4; dd++) {
                float4 k4 = *(const float4*)(KsT + (d + dd) * PAD + tx * 4);
                #pragma unroll
                for (int r = 0; r < 4; r++) {
                    s_[r][0] += qrow[r][dd] * k4.x;
                    s_[r][1] += qrow[r][dd] * k4.y;
                    s_[r][2] += qrow[r][dd] * k4.z;
                    s_[r][3] += qrow[r][dd] * k4.w;
                }
            }
        }

        bool diag = (kt == qb);
        #pragma unroll
        for (int r = 0; r < 4; r++)
            #pragma unroll
            for (int c = 0; c < 4; c++) {
                float v = s_[r][c] * scale;
                if (diag && (tx * 4 + c) > (ty * 4 + r)) v = -1e30f;
                s_[r][c] = v;
            }

        #pragma unroll
        for (int r = 0; r < 4; r++) {
            float mx = fmaxf(fmaxf(s_[r][0], s_[r][1]), fmaxf(s_[r][2], s_[r][3]));
            #pragma unroll
            for (int o = 8; o >= 1; o >>= 1)
                mx = fmaxf(mx, __shfl_xor_sync(0xffffffffu, mx, o));
            float m_new = fmaxf(m_i[r], mx);
            float alpha = __expf(m_i[r] - m_new);
            float p0 = __expf(s_[r][0] - m_new);
            float p1 = __expf(s_[r][1] - m_new);
            float p2 = __expf(s_[r][2] - m_new);
            float p3 = __expf(s_[r][3] - m_new);
            *(float4*)(Ps + (ty * 4 + r) * PAD + tx * 4) = make_float4(p0, p1, p2, p3);
            float sum = p0 + p1 + p2 + p3;
            #pragma unroll
            for (int o = 8; o >= 1; o >>= 1)
                sum += __shfl_xor_sync(0xffffffffu, sum, o);
            l_i[r] = l_i[r] * alpha + sum;
            m_i[r] = m_new;
            #pragma unroll
            for (int c = 0; c < 4; c++) acc[r][c] *= alpha;
        }
        __syncthreads();

        #pragma unroll 4
        for (int kk = 0; kk < BKV; kk += 4) {
            float prow[4][4];
            #pragma unroll
            for (int r = 0; r < 4; r++)
                *(float4*)prow[r] = *(const float4*)(Ps + (ty * 4 + r) * PAD + kk);
            #pragma unroll
            for (int j = 0; j < 4; j++) {
                float4 v4 = *(const float4*)(Vs + (kk + j) * PAD + tx * 4);
                #pragma unroll
                for (int r = 0; r < 4; r++) {
                    acc[r][0] += prow[r][j] * v4.x;
                    acc[r][1] += prow[r][j] * v4.y;
                    acc[r][2] += prow[r][j] * v4.z;
                    acc[r][3] += prow[r][j] * v4.w;
                }
            }
        }
    }

    #pragma unroll
    for (int r = 0; r < 4; r++) {
        float inv = 1.0f / l_i[r];
        float4 o = make_float4(acc[r][0] * inv, acc[r][1] * inv,
                               acc[r][2] * inv, acc[r][3] * inv);
        *(float4*)(O + (size_t)(q0 + ty * 4 + r) * DMODEL + col0 + tx * 4) = o;
    }
}

// ---------------------------------------------------------------------------
extern "C" void kernel_launch(void* const* d_in, const int* in_sizes, int n_in,
                              void* d_out, int out_size)
{
    const float* x  = (const float*)d_in[0];
    const float* Wq = (const float*)d_in[1];
    const float* bq = (const float*)d_in[2];
    const float* Wk = (const float*)d_in[3];
    const float* bk = (const float*)d_in[4];
    const float* Wv = (const float*)d_in[5];
    const float* bv = (const float*)d_in[6];
    const float* Wo = (const float*)d_in[7];
    const float* bo = (const float*)d_in[8];
    float* out = (float*)d_out;

    float *q, *k, *v, *attn;
    cudaGetSymbolAddress((void**)&q,    g_q);
    cudaGetSymbolAddress((void**)&k,    g_k);
    cudaGetSymbolAddress((void**)&v,    g_v);
    cudaGetSymbolAddress((void**)&attn, g_attn);

    __nv_bfloat16 *xhi, *xlo, *wqh, *wql, *wkh, *wkl, *wvh, *wvl, *woh, *wol;
    cudaGetSymbolAddress((void**)&xhi, g_xhi);
    cudaGetSymbolAddress((void**)&xlo, g_xlo);
    cudaGetSymbolAddress((void**)&wqh, g_wqhi);
    cudaGetSymbolAddress((void**)&wql, g_wqlo);
    cudaGetSymbolAddress((void**)&wkh, g_wkhi);
    cudaGetSymbolAddress((void**)&wkl, g_wklo);
    cudaGetSymbolAddress((void**)&wvh, g_wvhi);
    cudaGetSymbolAddress((void**)&wvl, g_wvlo);
    cudaGetSymbolAddress((void**)&woh, g_wohi);
    cudaGetSymbolAddress((void**)&wol, g_wolo);

    const int SMEM_ATTN = 4 * 64 * PAD * sizeof(float);
    cudaFuncSetAttribute(attn_kernel,
                         cudaFuncAttributeMaxDynamicSharedMemorySize, SMEM_ATTN);
    cudaFuncSetAttribute(gemm_mma_kernel,
                         cudaFuncAttributeMaxDynamicSharedMemorySize, GEMM_SMEM);

    const int NX4 = S_LEN * DMODEL / 4;
    const int NW4 = DMODEL * DMODEL / 4;

    // split inputs to bf16 hi/lo
    cvt_split_kernel<<<(NX4 + 255) / 256, 256>>>(x,  xhi, xlo, NX4);
    cvt_split_kernel<<<(NW4 + 255) / 256, 256>>>(Wq, wqh, wql, NW4);
    cvt_split_kernel<<<(NW4 + 255) / 256, 256>>>(Wk, wkh, wkl, NW4);
    cvt_split_kernel<<<(NW4 + 255) / 256, 256>>>(Wv, wvh, wvl, NW4);
    cvt_split_kernel<<<(NW4 + 255) / 256, 256>>>(Wo, woh, wol, NW4);

    dim3 ggrid(DMODEL / 128, S_LEN / 128);
    gemm_mma_kernel<<<ggrid, 256, GEMM_SMEM>>>(xhi, xlo, wqh, wql, bq, q, DMODEL);
    gemm_mma_kernel<<<ggrid, 256, GEMM_SMEM>>>(xhi, xlo, wkh, wkl, bk, k, DMODEL);
    gemm_mma_kernel<<<ggrid, 256, GEMM_SMEM>>>(xhi, xlo, wvh, wvl, bv, v, DMODEL);

    attn_kernel<<<dim3(S_LEN / BQ, NHEADS), 256, SMEM_ATTN>>>(q, k, v, attn);

    // reuse x split buffers for the attention output split
    cvt_split_kernel<<<(NX4 + 255) / 256, 256>>>(attn, xhi, xlo, NX4);
    gemm_mma_kernel<<<ggrid, 256, GEMM_SMEM>>>(xhi, xlo, woh, wol, bo, out, DMODEL);
}

// round 8
// speedup vs baseline: 2.7694x; 2.0631x over previous
#include <cuda_runtime.h>
#include <cuda_bf16.h>
#include <cstdint>
#include <math.h>

#define S_LEN   4096
#define DMODEL  1024
#define NHEADS  16
#define DK      64

// ---------------- scratch (__device__ globals: allocation-free) ------------
__device__ __nv_bfloat16 g_xhi[S_LEN * DMODEL];   // x hi; later reused: attn-out hi
__device__ __nv_bfloat16 g_xlo[S_LEN * DMODEL];   // x lo; later reused: attn-out lo
__device__ __nv_bfloat16 g_qhi[S_LEN * DMODEL];
__device__ __nv_bfloat16 g_qlo[S_LEN * DMODEL];
__device__ __nv_bfloat16 g_khi[S_LEN * DMODEL];
__device__ __nv_bfloat16 g_klo[S_LEN * DMODEL];
__device__ __nv_bfloat16 g_vhi[S_LEN * DMODEL];
__device__ __nv_bfloat16 g_vlo[S_LEN * DMODEL];
__device__ __nv_bfloat16 g_wqhi[DMODEL * DMODEL];
__device__ __nv_bfloat16 g_wqlo[DMODEL * DMODEL];
__device__ __nv_bfloat16 g_wkhi[DMODEL * DMODEL];
__device__ __nv_bfloat16 g_wklo[DMODEL * DMODEL];
__device__ __nv_bfloat16 g_wvhi[DMODEL * DMODEL];
__device__ __nv_bfloat16 g_wvlo[DMODEL * DMODEL];
__device__ __nv_bfloat16 g_wohi[DMODEL * DMODEL];
__device__ __nv_bfloat16 g_wolo[DMODEL * DMODEL];

// ---------------------------------------------------------------------------
// helpers
// ---------------------------------------------------------------------------
__global__ __launch_bounds__(256) void cvt_split_kernel(
    const float* __restrict__ src,
    __nv_bfloat16* __restrict__ hi, __nv_bfloat16* __restrict__ lo, int n4)
{
    int i = blockIdx.x * 256 + threadIdx.x;
    if (i >= n4) return;
    float4 v = ((const float4*)src)[i];
    __nv_bfloat16 h0 = __float2bfloat16(v.x);
    __nv_bfloat16 h1 = __float2bfloat16(v.y);
    __nv_bfloat16 h2 = __float2bfloat16(v.z);
    __nv_bfloat16 h3 = __float2bfloat16(v.w);
    __nv_bfloat16 l0 = __float2bfloat16(v.x - __bfloat162float(h0));
    __nv_bfloat16 l1 = __float2bfloat16(v.y - __bfloat162float(h1));
    __nv_bfloat16 l2 = __float2bfloat16(v.z - __bfloat162float(h2));
    __nv_bfloat16 l3 = __float2bfloat16(v.w - __bfloat162float(h3));
    ((__nv_bfloat162*)hi)[2 * i + 0] = __nv_bfloat162(h0, h1);
    ((__nv_bfloat162*)hi)[2 * i + 1] = __nv_bfloat162(h2, h3);
    ((__nv_bfloat162*)lo)[2 * i + 0] = __nv_bfloat162(l0, l1);
    ((__nv_bfloat162*)lo)[2 * i + 1] = __nv_bfloat162(l2, l3);
}

__device__ __forceinline__ void mma16816(float* c, const uint32_t* a,
                                         uint32_t b0, uint32_t b1) {
    asm volatile(
        "mma.sync.aligned.m16n8k16.row.col.f32.bf16.bf16.f32 "
        "{%0,%1,%2,%3}, {%4,%5,%6,%7}, {%8,%9}, {%0,%1,%2,%3};\n"
        : "+f"(c[0]), "+f"(c[1]), "+f"(c[2]), "+f"(c[3])
        : "r"(a[0]), "r"(a[1]), "r"(a[2]), "r"(a[3]), "r"(b0), "r"(b1));
}

__device__ __forceinline__ void ldm_x4(uint32_t* r, uint32_t addr) {
    asm volatile("ldmatrix.sync.aligned.m8n8.x4.shared.b16 {%0,%1,%2,%3}, [%4];"
        : "=r"(r[0]), "=r"(r[1]), "=r"(r[2]), "=r"(r[3]) : "r"(addr));
}

__device__ __forceinline__ void ldm_x4_t(uint32_t* r, uint32_t addr) {
    asm volatile("ldmatrix.sync.aligned.m8n8.x4.trans.shared.b16 {%0,%1,%2,%3}, [%4];"
        : "=r"(r[0]), "=r"(r[1]), "=r"(r[2]), "=r"(r[3]) : "r"(addr));
}

// hi/lo split of two floats, packed for mma (low half = first element)
__device__ __forceinline__ void split2(float x, float y, uint32_t& hi, uint32_t& lo) {
    __nv_bfloat16 hx = __float2bfloat16(x), hy = __float2bfloat16(y);
    __nv_bfloat16 lx = __float2bfloat16(x - __bfloat162float(hx));
    __nv_bfloat16 ly = __float2bfloat16(y - __bfloat162float(hy));
    __nv_bfloat162 h(hx, hy), l(lx, ly);
    hi = *(uint32_t*)&h; lo = *(uint32_t*)&l;
}

// ---------------------------------------------------------------------------
// bf16-split HMMA GEMM: C = (Ahi+Alo)[M,K] @ (Bhi+Blo)[N,K]^T + bias
// CTA 128x128, BK=32, 8 warps (32x64). ldmatrix fragment loads.
// Output: fp32 (Cf) OR bf16 hi/lo pair (Chi/Clo).
// ---------------------------------------------------------------------------
#define GBK      32
#define ROW_B    80
#define TILE_B   (128 * ROW_B)
#define STAGE_B  (4 * TILE_B)
#define GEMM_SMEM (2 * STAGE_B)

__global__ __launch_bounds__(256) void gemm_mma_kernel(
    const __nv_bfloat16* __restrict__ Ahi, const __nv_bfloat16* __restrict__ Alo,
    const __nv_bfloat16* __restrict__ Bhi, const __nv_bfloat16* __restrict__ Blo,
    const float* __restrict__ bias, float* __restrict__ Cf,
    __nv_bfloat16* __restrict__ Chi, __nv_bfloat16* __restrict__ Clo, int K)
{
    extern __shared__ char sm_raw[];
    int tid  = threadIdx.x;
    int lane = tid & 31, wid = tid >> 5;
    int g = lane >> 2;
    int q = lane & 3;
    int warpM = (wid & 3) * 32;
    int warpN = (wid >> 2) * 64;
    int n0 = blockIdx.x * 128;
    int m0 = blockIdx.y * 128;

    uint32_t sbase = (uint32_t)__cvta_generic_to_shared(sm_raw);

    float acc[2][8][4] = {};
    const __nv_bfloat16* srcs[4] = {Ahi, Alo, Bhi, Blo};

    auto issue_loads = [&](int stage, int k0) {
        uint32_t st = sbase + stage * STAGE_B;
        int row4 = tid >> 2;
        int ch   = tid & 3;
        #pragma unroll
        for (int t = 0; t < 4; t++) {
            int rbase = (t < 2) ? m0 : n0;
            #pragma unroll
            for (int h = 0; h < 2; h++) {
                int row = row4 + h * 64;
                const void* gp = srcs[t] + (size_t)(rbase + row) * K + k0 + ch * 8;
                uint32_t dp = st + t * TILE_B + row * ROW_B + ch * 16;
                asm volatile("cp.async.cg.shared.global [%0], [%1], 16;\n"
                             :: "r"(dp), "l"(gp));
            }
        }
        asm volatile("cp.async.commit_group;\n" ::: "memory");
    };

    auto compute = [&](int stage) {
        uint32_t st   = sbase + stage * STAGE_B;
        uint32_t sA = st;             // Ahi; Alo at +TILE_B
        uint32_t sB = st + 2 * TILE_B; // Bhi; Blo at +TILE_B
        #pragma unroll
        for (int ks = 0; ks < GBK; ks += 16) {
            uint32_t ah[2][4], al[2][4];
            #pragma unroll
            for (int i = 0; i < 2; i++) {
                uint32_t ad = sA + (uint32_t)((warpM + i * 16 + (lane & 15)) * ROW_B
                                              + (ks + (lane >> 4) * 8) * 2);
                ldm_x4(ah[i], ad);
                ldm_x4(al[i], ad + TILE_B);
            }
            int grp = lane >> 3;
            #pragma unroll
            for (int jp = 0; jp < 4; jp++) {
                uint32_t bd = sB + (uint32_t)((warpN + (jp * 2 + (grp >> 1)) * 8 + (lane & 7)) * ROW_B
                                              + (ks + (grp & 1) * 8) * 2);
                uint32_t bh[4], bl[4];
                ldm_x4(bh, bd);
                ldm_x4(bl, bd + TILE_B);
                #pragma unroll
                for (int i = 0; i < 2; i++) {
                    mma16816(acc[i][jp * 2],     ah[i], bh[0], bh[1]);
                    mma16816(acc[i][jp * 2],     ah[i], bl[0], bl[1]);
                    mma16816(acc[i][jp * 2],     al[i], bh[0], bh[1]);
                    mma16816(acc[i][jp * 2 + 1], ah[i], bh[2], bh[3]);
                    mma16816(acc[i][jp * 2 + 1], ah[i], bl[2], bl[3]);
                    mma16816(acc[i][jp * 2 + 1], al[i], bh[2], bh[3]);
                }
            }
        }
    };

    const int NITER = K / GBK;
    issue_loads(0, 0);
    for (int it = 0; it < NITER; it++) {
        if (it + 1 < NITER) {
            issue_loads((it + 1) & 1, (it + 1) * GBK);
            asm volatile("cp.async.wait_group 1;\n" ::: "memory");
        } else {
            asm volatile("cp.async.wait_group 0;\n" ::: "memory");
        }
        __syncthreads();
        compute(it & 1);
        __syncthreads();
    }

    // --- epilogue ---
    #pragma unroll
    for (int i = 0; i < 2; i++) {
        int r0 = m0 + warpM + i * 16 + g;
        #pragma unroll
        for (int j = 0; j < 8; j++) {
            int c = n0 + warpN + j * 8 + q * 2;
            float2 b2 = *(const float2*)(bias + c);
            float o0 = acc[i][j][0] + b2.x, o1 = acc[i][j][1] + b2.y;
            float o2 = acc[i][j][2] + b2.x, o3 = acc[i][j][3] + b2.y;
            if (Cf) {
                *(float2*)(Cf + (size_t)r0 * DMODEL + c) = make_float2(o0, o1);
                *(float2*)(Cf + (size_t)(r0 + 8) * DMODEL + c) = make_float2(o2, o3);
            } else {
                uint32_t hp, lp;
                split2(o0, o1, hp, lp);
                *(uint32_t*)(Chi + (size_t)r0 * DMODEL + c) = hp;
                *(uint32_t*)(Clo + (size_t)r0 * DMODEL + c) = lp;
                split2(o2, o3, hp, lp);
                *(uint32_t*)(Chi + (size_t)(r0 + 8) * DMODEL + c) = hp;
                *(uint32_t*)(Clo + (size_t)(r0 + 8) * DMODEL + c) = lp;
            }
        }
    }
}

// ---------------------------------------------------------------------------
// HMMA flash attention, bf16 hi/lo split, causal.
// Grid (32 q-tiles, 16 heads), 256 threads (8 warps x 16 q-rows).
// smem: Q tile 128x64 hi+lo (144B rows) + KV tile 64x64 x4 arrays.
// ---------------------------------------------------------------------------
#define AROW    144
#define QT_B    (128 * AROW)          // 18432 per Q array
#define KV_B    (64 * AROW)           // 9216 per KV array
#define KV_BASE (2 * QT_B)            // 36864
#define ATTN_SMEM (KV_BASE + 4 * KV_B) // 73728

__global__ __launch_bounds__(256) void attn_mma_kernel(
    const __nv_bfloat16* __restrict__ Qhi, const __nv_bfloat16* __restrict__ Qlo,
    const __nv_bfloat16* __restrict__ Khi, const __nv_bfloat16* __restrict__ Klo,
    const __nv_bfloat16* __restrict__ Vhi, const __nv_bfloat16* __restrict__ Vlo,
    __nv_bfloat16* __restrict__ Ohi, __nv_bfloat16* __restrict__ Olo)
{
    extern __shared__ char sm_raw[];
    uint32_t sb = (uint32_t)__cvta_generic_to_shared(sm_raw);

    int tid  = threadIdx.x;
    int lane = tid & 31, w = tid >> 5;
    int g = lane >> 2, q = lane & 3;
    int head = blockIdx.y;
    int qb = blockIdx.x;
    int q0 = qb * 128;
    int col0 = head * DK;

    // ---- load Q tile (hi+lo): 128 rows x 64 cols ----
    {
        const __nv_bfloat16* srcs[2] = {Qhi, Qlo};
        #pragma unroll
        for (int arr = 0; arr < 2; arr++)
            for (int c = tid; c < 1024; c += 256) {
                int row = c >> 3, ch = c & 7;
                const void* gp = srcs[arr] + (size_t)(q0 + row) * DMODEL + col0 + ch * 8;
                uint32_t dp = sb + arr * QT_B + row * AROW + ch * 16;
                asm volatile("cp.async.cg.shared.global [%0], [%1], 16;\n"
                             :: "r"(dp), "l"(gp));
            }
        asm volatile("cp.async.commit_group;\n" ::: "memory");
    }

    const __nv_bfloat16* kvsrc[4] = {Khi, Klo, Vhi, Vlo};
    auto issue_kv = [&](int kt) {
        int k0 = kt * 64;
        #pragma unroll
        for (int arr = 0; arr < 4; arr++)
            for (int c = tid; c < 512; c += 256) {
                int row = c >> 3, ch = c & 7;
                const void* gp = kvsrc[arr] + (size_t)(k0 + row) * DMODEL + col0 + ch * 8;
                uint32_t dp = sb + KV_BASE + arr * KV_B + row * AROW + ch * 16;
                asm volatile("cp.async.cg.shared.global [%0], [%1], 16;\n"
                             :: "r"(dp), "l"(gp));
            }
        asm volatile("cp.async.commit_group;\n" ::: "memory");
    };

    issue_kv(0);
    asm volatile("cp.async.wait_group 0;\n" ::: "memory");
    __syncthreads();

    float o[8][4] = {};
    float m0r = -1e30f, m1r = -1e30f, l0r = 0.0f, l1r = 0.0f;
    const int r0 = q0 + w * 16;
    const int nt = 2 * qb + 2;

    for (int kt = 0; kt < nt; kt++) {
        int k0 = kt * 64;
        if (k0 <= r0 + 15) {
            uint32_t sQh = sb, sQl = sb + QT_B;
            uint32_t sKh = sb + KV_BASE, sKl = sKh + KV_B;
            uint32_t sVh = sKh + 2 * KV_B, sVl = sKh + 3 * KV_B;
            int grp = lane >> 3;

            // ---- S = Q @ K^T (3-pass split) ----
            float s[8][4] = {};
            #pragma unroll
            for (int t = 0; t < 4; t++) {
                uint32_t qh[4], ql[4];
                uint32_t qa = sQh + (uint32_t)((w * 16 + (lane & 15)) * AROW
                                               + (t * 16 + (lane >> 4) * 8) * 2);
                ldm_x4(qh, qa);
                ldm_x4(ql, qa + QT_B);
                #pragma unroll
                for (int jp = 0; jp < 4; jp++) {
                    uint32_t bd = sKh + (uint32_t)(((jp * 2 + (grp >> 1)) * 8 + (lane & 7)) * AROW
                                                   + (t * 16 + (grp & 1) * 8) * 2);
                    uint32_t bh[4], bl[4];
                    ldm_x4(bh, bd);
                    ldm_x4(bl, bd + KV_B);
                    mma16816(s[jp * 2],     qh, bh[0], bh[1]);
                    mma16816(s[jp * 2],     qh, bl[0], bl[1]);
                    mma16816(s[jp * 2],     ql, bh[0], bh[1]);
                    mma16816(s[jp * 2 + 1], qh, bh[2], bh[3]);
                    mma16816(s[jp * 2 + 1], qh, bl[2], bl[3]);
                    mma16816(s[jp * 2 + 1], ql, bh[2], bh[3]);
                }
            }

            // ---- scale + causal mask ----
            bool need_mask = (k0 + 63 > r0);
            #pragma unroll
            for (int nb = 0; nb < 8; nb++)
                #pragma unroll
                for (int ci = 0; ci < 4; ci++) {
                    float v = s[nb][ci] * 0.125f;
                    if (need_mask) {
                        int row = r0 + g + (ci >> 1) * 8;
                        int key = k0 + nb * 8 + 2 * q + (ci & 1);
                        if (key > row) v = -1e30f;
                    }
                    s[nb][ci] = v;
                }

            // ---- online softmax (rows g and g+8) ----
            float mx0 = -1e30f, mx1 = -1e30f;
            #pragma unroll
            for (int nb = 0; nb < 8; nb++) {
                mx0 = fmaxf(mx0, fmaxf(s[nb][0], s[nb][1]));
                mx1 = fmaxf(mx1, fmaxf(s[nb][2], s[nb][3]));
            }
            mx0 = fmaxf(mx0, __shfl_xor_sync(0xffffffffu, mx0, 1));
            mx0 = fmaxf(mx0, __shfl_xor_sync(0xffffffffu, mx0, 2));
            mx1 = fmaxf(mx1, __shfl_xor_sync(0xffffffffu, mx1, 1));
            mx1 = fmaxf(mx1, __shfl_xor_sync(0xffffffffu, mx1, 2));
            float mn0 = fmaxf(m0r, mx0), mn1 = fmaxf(m1r, mx1);
            float a0 = __expf(m0r - mn0), a1 = __expf(m1r - mn1);
            float ls0 = 0.0f, ls1 = 0.0f;
            #pragma unroll
            for (int nb = 0; nb < 8; nb++) {
                float p0 = __expf(s[nb][0] - mn0);
                float p1 = __expf(s[nb][1] - mn0);
                float p2 = __expf(s[nb][2] - mn1);
                float p3 = __expf(s[nb][3] - mn1);
                s[nb][0] = p0; s[nb][1] = p1; s[nb][2] = p2; s[nb][3] = p3;
                ls0 += p0 + p1; ls1 += p2 + p3;
            }
            ls0 += __shfl_xor_sync(0xffffffffu, ls0, 1);
            ls0 += __shfl_xor_sync(0xffffffffu, ls0, 2);
            ls1 += __shfl_xor_sync(0xffffffffu, ls1, 1);
            ls1 += __shfl_xor_sync(0xffffffffu, ls1, 2);
            l0r = l0r * a0 + ls0; l1r = l1r * a1 + ls1;
            m0r = mn0; m1r = mn1;
            #pragma unroll
            for (int nb = 0; nb < 8; nb++) {
                o[nb][0] *= a0; o[nb][1] *= a0;
                o[nb][2] *= a1; o[nb][3] *= a1;
            }

            // ---- O += P @ V (3-pass split; P frags from S accumulators) ----
            #pragma unroll
            for (int t = 0; t < 4; t++) {
                uint32_t ph[4], pl[4];
                split2(s[2 * t][0],     s[2 * t][1],     ph[0], pl[0]);
                split2(s[2 * t][2],     s[2 * t][3],     ph[1], pl[1]);
                split2(s[2 * t + 1][0], s[2 * t + 1][1], ph[2], pl[2]);
                split2(s[2 * t + 1][2], s[2 * t + 1][3], ph[3], pl[3]);
                #pragma unroll
                for (int jp = 0; jp < 4; jp++) {
                    uint32_t vd = sVh + (uint32_t)((16 * t + (grp & 1) * 8 + (lane & 7)) * AROW
                                                   + ((jp * 2 + (grp >> 1)) * 8) * 2);
                    uint32_t vh[4], vl[4];
                    ldm_x4_t(vh, vd);
                    ldm_x4_t(vl, vd + KV_B);
                    mma16816(o[jp * 2],     ph, vh[0], vh[1]);
                    mma16816(o[jp * 2],     ph, vl[0], vl[1]);
                    mma16816(o[jp * 2],     pl, vh[0], vh[1]);
                    mma16816(o[jp * 2 + 1], ph, vh[2], vh[3]);
                    mma16816(o[jp * 2 + 1], ph, vl[2], vl[3]);
                    mma16816(o[jp * 2 + 1], pl, vh[2], vh[3]);
                }
            }
        }

        if (kt + 1 < nt) {
            __syncthreads();            // everyone done reading this KV tile
            issue_kv(kt + 1);
            asm volatile("cp.async.wait_group 0;\n" ::: "memory");
            __syncthreads();
        }
    }

    // ---- epilogue: normalize, hi/lo split, store ----
    float inv0 = 1.0f / l0r, inv1 = 1.0f / l1r;
    int row0 = q0 + w * 16 + g;
    int row1 = row0 + 8;
    #pragma unroll
    for (int nb = 0; nb < 8; nb++) {
        int c = col0 + nb * 8 + 2 * q;
        uint32_t hp, lp;
        split2(o[nb][0] * inv0, o[nb][1] * inv0, hp, lp);
        *(uint32_t*)(Ohi + (size_t)row0 * DMODEL + c) = hp;
        *(uint32_t*)(Olo + (size_t)row0 * DMODEL + c) = lp;
        split2(o[nb][2] * inv1, o[nb][3] * inv1, hp, lp);
        *(uint32_t*)(Ohi + (size_t)row1 * DMODEL + c) = hp;
        *(uint32_t*)(Olo + (size_t)row1 * DMODEL + c) = lp;
    }
}

// ---------------------------------------------------------------------------
extern "C" void kernel_launch(void* const* d_in, const int* in_sizes, int n_in,
                              void* d_out, int out_size)
{
    const float* x  = (const float*)d_in[0];
    const float* Wq = (const float*)d_in[1];
    const float* bq = (const float*)d_in[2];
    const float* Wk = (const float*)d_in[3];
    const float* bk = (const float*)d_in[4];
    const float* Wv = (const float*)d_in[5];
    const float* bv = (const float*)d_in[6];
    const float* Wo = (const float*)d_in[7];
    const float* bo = (const float*)d_in[8];
    float* out = (float*)d_out;

    __nv_bfloat16 *xhi, *xlo, *qhi, *qlo, *khi, *klo, *vhi, *vlo;
    __nv_bfloat16 *wqh, *wql, *wkh, *wkl, *wvh, *wvl, *woh, *wol;
    cudaGetSymbolAddress((void**)&xhi, g_xhi);
    cudaGetSymbolAddress((void**)&xlo, g_xlo);
    cudaGetSymbolAddress((void**)&qhi, g_qhi);
    cudaGetSymbolAddress((void**)&qlo, g_qlo);
    cudaGetSymbolAddress((void**)&khi, g_khi);
    cudaGetSymbolAddress((void**)&klo, g_klo);
    cudaGetSymbolAddress((void**)&vhi, g_vhi);
    cudaGetSymbolAddress((void**)&vlo, g_vlo);
    cudaGetSymbolAddress((void**)&wqh, g_wqhi);
    cudaGetSymbolAddress((void**)&wql, g_wqlo);
    cudaGetSymbolAddress((void**)&wkh, g_wkhi);
    cudaGetSymbolAddress((void**)&wkl, g_wklo);
    cudaGetSymbolAddress((void**)&wvh, g_wvhi);
    cudaGetSymbolAddress((void**)&wvl, g_wvlo);
    cudaGetSymbolAddress((void**)&woh, g_wohi);
    cudaGetSymbolAddress((void**)&wol, g_wolo);

    cudaFuncSetAttribute(gemm_mma_kernel,
                         cudaFuncAttributeMaxDynamicSharedMemorySize, GEMM_SMEM);
    cudaFuncSetAttribute(attn_mma_kernel,
                         cudaFuncAttributeMaxDynamicSharedMemorySize, ATTN_SMEM);

    const int NX4 = S_LEN * DMODEL / 4;
    const int NW4 = DMODEL * DMODEL / 4;

    cvt_split_kernel<<<(NX4 + 255) / 256, 256>>>(x,  xhi, xlo, NX4);
    cvt_split_kernel<<<(NW4 + 255) / 256, 256>>>(Wq, wqh, wql, NW4);
    cvt_split_kernel<<<(NW4 + 255) / 256, 256>>>(Wk, wkh, wkl, NW4);
    cvt_split_kernel<<<(NW4 + 255) / 256, 256>>>(Wv, wvh, wvl, NW4);
    cvt_split_kernel<<<(NW4 + 255) / 256, 256>>>(Wo, woh, wol, NW4);

    dim3 ggrid(DMODEL / 128, S_LEN / 128);
    gemm_mma_kernel<<<ggrid, 256, GEMM_SMEM>>>(xhi, xlo, wqh, wql, bq,
                                               nullptr, qhi, qlo, DMODEL);
    gemm_mma_kernel<<<ggrid, 256, GEMM_SMEM>>>(xhi, xlo, wkh, wkl, bk,
                                               nullptr, khi, klo, DMODEL);
    gemm_mma_kernel<<<ggrid, 256, GEMM_SMEM>>>(xhi, xlo, wvh, wvl, bv,
                                               nullptr, vhi, vlo, DMODEL);

    // attention writes its bf16 hi/lo output into xhi/xlo (x splits are consumed)
    attn_mma_kernel<<<dim3(S_LEN / 128, NHEADS), 256, ATTN_SMEM>>>(
        qhi, qlo, khi, klo, vhi, vlo, xhi, xlo);

    gemm_mma_kernel<<<ggrid, 256, GEMM_SMEM>>>(xhi, xlo, woh, wol, bo,
                                               out, nullptr, nullptr, DMODEL);
}

// round 9
// speedup vs baseline: 3.0712x; 1.1090x over previous
#include <cuda_runtime.h>
#include <cuda_bf16.h>
#include <cstdint>
#include <math.h>

#define S_LEN   4096
#define DMODEL  1024
#define NHEADS  16
#define DK      64

// ---------------- scratch (__device__ globals: allocation-free) ------------
__device__ __nv_bfloat16 g_xhi[S_LEN * DMODEL];   // x hi; later reused: attn-out hi
__device__ __nv_bfloat16 g_xlo[S_LEN * DMODEL];   // x lo; later reused: attn-out lo
__device__ __nv_bfloat16 g_qhi[S_LEN * DMODEL];
__device__ __nv_bfloat16 g_qlo[S_LEN * DMODEL];
__device__ __nv_bfloat16 g_khi[S_LEN * DMODEL];
__device__ __nv_bfloat16 g_klo[S_LEN * DMODEL];
__device__ __nv_bfloat16 g_vhi[S_LEN * DMODEL];
__device__ __nv_bfloat16 g_vlo[S_LEN * DMODEL];
__device__ __nv_bfloat16 g_wqhi[DMODEL * DMODEL];
__device__ __nv_bfloat16 g_wqlo[DMODEL * DMODEL];
__device__ __nv_bfloat16 g_wkhi[DMODEL * DMODEL];
__device__ __nv_bfloat16 g_wklo[DMODEL * DMODEL];
__device__ __nv_bfloat16 g_wvhi[DMODEL * DMODEL];
__device__ __nv_bfloat16 g_wvlo[DMODEL * DMODEL];
__device__ __nv_bfloat16 g_wohi[DMODEL * DMODEL];
__device__ __nv_bfloat16 g_wolo[DMODEL * DMODEL];

// ---------------------------------------------------------------------------
// helpers
// ---------------------------------------------------------------------------
__global__ __launch_bounds__(256) void cvt_split_kernel(
    const float* __restrict__ src,
    __nv_bfloat16* __restrict__ hi, __nv_bfloat16* __restrict__ lo, int n4)
{
    int i = blockIdx.x * 256 + threadIdx.x;
    if (i >= n4) return;
    float4 v = ((const float4*)src)[i];
    __nv_bfloat16 h0 = __float2bfloat16(v.x);
    __nv_bfloat16 h1 = __float2bfloat16(v.y);
    __nv_bfloat16 h2 = __float2bfloat16(v.z);
    __nv_bfloat16 h3 = __float2bfloat16(v.w);
    __nv_bfloat16 l0 = __float2bfloat16(v.x - __bfloat162float(h0));
    __nv_bfloat16 l1 = __float2bfloat16(v.y - __bfloat162float(h1));
    __nv_bfloat16 l2 = __float2bfloat16(v.z - __bfloat162float(h2));
    __nv_bfloat16 l3 = __float2bfloat16(v.w - __bfloat162float(h3));
    ((__nv_bfloat162*)hi)[2 * i + 0] = __nv_bfloat162(h0, h1);
    ((__nv_bfloat162*)hi)[2 * i + 1] = __nv_bfloat162(h2, h3);
    ((__nv_bfloat162*)lo)[2 * i + 0] = __nv_bfloat162(l0, l1);
    ((__nv_bfloat162*)lo)[2 * i + 1] = __nv_bfloat162(l2, l3);
}

__device__ __forceinline__ void mma16816(float* c, const uint32_t* a,
                                         uint32_t b0, uint32_t b1) {
    asm volatile(
        "mma.sync.aligned.m16n8k16.row.col.f32.bf16.bf16.f32 "
        "{%0,%1,%2,%3}, {%4,%5,%6,%7}, {%8,%9}, {%0,%1,%2,%3};\n"
        : "+f"(c[0]), "+f"(c[1]), "+f"(c[2]), "+f"(c[3])
        : "r"(a[0]), "r"(a[1]), "r"(a[2]), "r"(a[3]), "r"(b0), "r"(b1));
}

__device__ __forceinline__ void ldm_x4(uint32_t* r, uint32_t addr) {
    asm volatile("ldmatrix.sync.aligned.m8n8.x4.shared.b16 {%0,%1,%2,%3}, [%4];"
        : "=r"(r[0]), "=r"(r[1]), "=r"(r[2]), "=r"(r[3]) : "r"(addr));
}

__device__ __forceinline__ void ldm_x4_t(uint32_t* r, uint32_t addr) {
    asm volatile("ldmatrix.sync.aligned.m8n8.x4.trans.shared.b16 {%0,%1,%2,%3}, [%4];"
        : "=r"(r[0]), "=r"(r[1]), "=r"(r[2]), "=r"(r[3]) : "r"(addr));
}

__device__ __forceinline__ void split2(float x, float y, uint32_t& hi, uint32_t& lo) {
    __nv_bfloat16 hx = __float2bfloat16(x), hy = __float2bfloat16(y);
    __nv_bfloat16 lx = __float2bfloat16(x - __bfloat162float(hx));
    __nv_bfloat16 ly = __float2bfloat16(y - __bfloat162float(hy));
    __nv_bfloat162 h(hx, hy), l(lx, ly);
    hi = *(uint32_t*)&h; lo = *(uint32_t*)&l;
}

// ---------------------------------------------------------------------------
// bf16-split HMMA GEMM: C = (Ahi+Alo)[M,K] @ (Bhi+Blo)[N,K]^T + bias
// CTA 128x128, BK=64, 8 warps (32x64). One __syncthreads per K-iter;
// cp.async prefetch issued BEFORE compute so the transfer hides under MMA.
// ---------------------------------------------------------------------------
#define GBK      64
#define ROW_B    144               // 128B data + 16B pad
#define TILE_B   (128 * ROW_B)     // 18432
#define STAGE_B  (4 * TILE_B)      // 73728
#define GEMM_SMEM (2 * STAGE_B)    // 147456

__global__ __launch_bounds__(256) void gemm_mma_kernel(
    const __nv_bfloat16* __restrict__ Ahi, const __nv_bfloat16* __restrict__ Alo,
    const __nv_bfloat16* __restrict__ Bhi, const __nv_bfloat16* __restrict__ Blo,
    const float* __restrict__ bias, float* __restrict__ Cf,
    __nv_bfloat16* __restrict__ Chi, __nv_bfloat16* __restrict__ Clo, int K)
{
    extern __shared__ char sm_raw[];
    int tid  = threadIdx.x;
    int lane = tid & 31, wid = tid >> 5;
    int g = lane >> 2;
    int q = lane & 3;
    int warpM = (wid & 3) * 32;
    int warpN = (wid >> 2) * 64;
    int n0 = blockIdx.x * 128;
    int m0 = blockIdx.y * 128;

    uint32_t sbase = (uint32_t)__cvta_generic_to_shared(sm_raw);

    float acc[2][8][4] = {};
    const __nv_bfloat16* srcs[4] = {Ahi, Alo, Bhi, Blo};

    // 4 tiles of [128][64] bf16 (128B rows), 16B chunks, 1024 chunks/tile
    auto issue_loads = [&](int stage, int k0) {
        uint32_t st = sbase + stage * STAGE_B;
        #pragma unroll
        for (int t = 0; t < 4; t++) {
            int rbase = (t < 2) ? m0 : n0;
            #pragma unroll
            for (int c = 0; c < 4; c++) {
                int lin = tid + c * 256;        // 0..1023
                int row = lin >> 3, ch = lin & 7;
                const void* gp = srcs[t] + (size_t)(rbase + row) * K + k0 + ch * 8;
                uint32_t dp = st + t * TILE_B + row * ROW_B + ch * 16;
                asm volatile("cp.async.cg.shared.global [%0], [%1], 16;\n"
                             :: "r"(dp), "l"(gp));
            }
        }
        asm volatile("cp.async.commit_group;\n" ::: "memory");
    };

    auto compute = [&](int stage) {
        uint32_t st = sbase + stage * STAGE_B;
        uint32_t sA = st;               // Ahi; Alo at +TILE_B
        uint32_t sB = st + 2 * TILE_B;  // Bhi; Blo at +TILE_B
        int grp = lane >> 3;
        #pragma unroll
        for (int ks = 0; ks < GBK; ks += 16) {
            uint32_t ah[2][4], al[2][4];
            #pragma unroll
            for (int i = 0; i < 2; i++) {
                uint32_t ad = sA + (uint32_t)((warpM + i * 16 + (lane & 15)) * ROW_B
                                              + (ks + (lane >> 4) * 8) * 2);
                ldm_x4(ah[i], ad);
                ldm_x4(al[i], ad + TILE_B);
            }
            #pragma unroll
            for (int jp = 0; jp < 4; jp++) {
                uint32_t bd = sB + (uint32_t)((warpN + (jp * 2 + (grp >> 1)) * 8 + (lane & 7)) * ROW_B
                                              + (ks + (grp & 1) * 8) * 2);
                uint32_t bh[4], bl[4];
                ldm_x4(bh, bd);
                ldm_x4(bl, bd + TILE_B);
                #pragma unroll
                for (int i = 0; i < 2; i++) {
                    mma16816(acc[i][jp * 2],     ah[i], bh[0], bh[1]);
                    mma16816(acc[i][jp * 2],     ah[i], bl[0], bl[1]);
                    mma16816(acc[i][jp * 2],     al[i], bh[0], bh[1]);
                    mma16816(acc[i][jp * 2 + 1], ah[i], bh[2], bh[3]);
                    mma16816(acc[i][jp * 2 + 1], ah[i], bl[2], bl[3]);
                    mma16816(acc[i][jp * 2 + 1], al[i], bh[2], bh[3]);
                }
            }
        }
    };

    const int NITER = K / GBK;    // 16
    issue_loads(0, 0);
    asm volatile("cp.async.wait_group 0;\n" ::: "memory");
    __syncthreads();
    for (int it = 0; it < NITER; it++) {
        if (it + 1 < NITER) issue_loads((it + 1) & 1, (it + 1) * GBK);
        compute(it & 1);
        if (it + 1 < NITER) {
            asm volatile("cp.async.wait_group 0;\n" ::: "memory");
            __syncthreads();
        }
    }

    // --- epilogue ---
    #pragma unroll
    for (int i = 0; i < 2; i++) {
        int r0 = m0 + warpM + i * 16 + g;
        #pragma unroll
        for (int j = 0; j < 8; j++) {
            int c = n0 + warpN + j * 8 + q * 2;
            float2 b2 = *(const float2*)(bias + c);
            float o0 = acc[i][j][0] + b2.x, o1 = acc[i][j][1] + b2.y;
            float o2 = acc[i][j][2] + b2.x, o3 = acc[i][j][3] + b2.y;
            if (Cf) {
                *(float2*)(Cf + (size_t)r0 * DMODEL + c) = make_float2(o0, o1);
                *(float2*)(Cf + (size_t)(r0 + 8) * DMODEL + c) = make_float2(o2, o3);
            } else {
                uint32_t hp, lp;
                split2(o0, o1, hp, lp);
                *(uint32_t*)(Chi + (size_t)r0 * DMODEL + c) = hp;
                *(uint32_t*)(Clo + (size_t)r0 * DMODEL + c) = lp;
                split2(o2, o3, hp, lp);
                *(uint32_t*)(Chi + (size_t)(r0 + 8) * DMODEL + c) = hp;
                *(uint32_t*)(Clo + (size_t)(r0 + 8) * DMODEL + c) = lp;
            }
        }
    }
}

// ---------------------------------------------------------------------------
// HMMA flash attention, bf16 hi/lo split, causal.
// Grid (32 q-tiles REVERSED, 16 heads), 256 threads (8 warps x 16 q-rows).
// KV double-buffered; one __syncthreads per KV tile; heavy CTAs launch first.
// ---------------------------------------------------------------------------
#define AROW     144
#define QT_B     (128 * AROW)          // 18432 per Q array
#define KV_B     (64 * AROW)           // 9216 per KV array
#define KV_BASE  (2 * QT_B)            // 36864
#define KVSTG_B  (4 * KV_B)            // 36864 per stage
#define ATTN_SMEM (KV_BASE + 2 * KVSTG_B)  // 110592

__global__ __launch_bounds__(256) void attn_mma_kernel(
    const __nv_bfloat16* __restrict__ Qhi, const __nv_bfloat16* __restrict__ Qlo,
    const __nv_bfloat16* __restrict__ Khi, const __nv_bfloat16* __restrict__ Klo,
    const __nv_bfloat16* __restrict__ Vhi, const __nv_bfloat16* __restrict__ Vlo,
    __nv_bfloat16* __restrict__ Ohi, __nv_bfloat16* __restrict__ Olo)
{
    extern __shared__ char sm_raw[];
    uint32_t sb = (uint32_t)__cvta_generic_to_shared(sm_raw);

    int tid  = threadIdx.x;
    int lane = tid & 31, w = tid >> 5;
    int g = lane >> 2, q = lane & 3;
    int head = blockIdx.y;
    int qb = (int)(gridDim.x - 1 - blockIdx.x);   // heavy tiles first
    int q0 = qb * 128;
    int col0 = head * DK;

    // ---- Q tile (hi+lo): 128 rows x 64 cols ----
    {
        const __nv_bfloat16* srcs[2] = {Qhi, Qlo};
        #pragma unroll
        for (int arr = 0; arr < 2; arr++)
            for (int c = tid; c < 1024; c += 256) {
                int row = c >> 3, ch = c & 7;
                const void* gp = srcs[arr] + (size_t)(q0 + row) * DMODEL + col0 + ch * 8;
                uint32_t dp = sb + arr * QT_B + row * AROW + ch * 16;
                asm volatile("cp.async.cg.shared.global [%0], [%1], 16;\n"
                             :: "r"(dp), "l"(gp));
            }
        asm volatile("cp.async.commit_group;\n" ::: "memory");
    }

    const __nv_bfloat16* kvsrc[4] = {Khi, Klo, Vhi, Vlo};
    auto issue_kv = [&](int kt, int stage) {
        int k0 = kt * 64;
        uint32_t st = sb + KV_BASE + stage * KVSTG_B;
        #pragma unroll
        for (int arr = 0; arr < 4; arr++)
            for (int c = tid; c < 512; c += 256) {
                int row = c >> 3, ch = c & 7;
                const void* gp = kvsrc[arr] + (size_t)(k0 + row) * DMODEL + col0 + ch * 8;
                uint32_t dp = st + arr * KV_B + row * AROW + ch * 16;
                asm volatile("cp.async.cg.shared.global [%0], [%1], 16;\n"
                             :: "r"(dp), "l"(gp));
            }
        asm volatile("cp.async.commit_group;\n" ::: "memory");
    };

    issue_kv(0, 0);
    asm volatile("cp.async.wait_group 0;\n" ::: "memory");
    __syncthreads();

    float o[8][4] = {};
    float m0r = -1e30f, m1r = -1e30f, l0r = 0.0f, l1r = 0.0f;
    const int r0 = q0 + w * 16;
    const int nt = 2 * qb + 2;
    int grp = lane >> 3;

    for (int kt = 0; kt < nt; kt++) {
        int k0 = kt * 64;
        if (kt + 1 < nt) issue_kv(kt + 1, (kt + 1) & 1);

        if (k0 <= r0 + 15) {
            uint32_t st  = sb + KV_BASE + (kt & 1) * KVSTG_B;
            uint32_t sQh = sb;
            uint32_t sKh = st;
            uint32_t sVh = st + 2 * KV_B;

            // ---- S = Q @ K^T (3-pass split) ----
            float s[8][4] = {};
            #pragma unroll
            for (int t = 0; t < 4; t++) {
                uint32_t qh[4], ql[4];
                uint32_t qa = sQh + (uint32_t)((w * 16 + (lane & 15)) * AROW
                                               + (t * 16 + (lane >> 4) * 8) * 2);
                ldm_x4(qh, qa);
                ldm_x4(ql, qa + QT_B);
                #pragma unroll
                for (int jp = 0; jp < 4; jp++) {
                    uint32_t bd = sKh + (uint32_t)(((jp * 2 + (grp >> 1)) * 8 + (lane & 7)) * AROW
                                                   + (t * 16 + (grp & 1) * 8) * 2);
                    uint32_t bh[4], bl[4];
                    ldm_x4(bh, bd);
                    ldm_x4(bl, bd + KV_B);
                    mma16816(s[jp * 2],     qh, bh[0], bh[1]);
                    mma16816(s[jp * 2],     qh, bl[0], bl[1]);
                    mma16816(s[jp * 2],     ql, bh[0], bh[1]);
                    mma16816(s[jp * 2 + 1], qh, bh[2], bh[3]);
                    mma16816(s[jp * 2 + 1], qh, bl[2], bl[3]);
                    mma16816(s[jp * 2 + 1], ql, bh[2], bh[3]);
                }
            }

            // ---- scale + causal mask ----
            bool need_mask = (k0 + 63 > r0);
            #pragma unroll
            for (int nb = 0; nb < 8; nb++)
                #pragma unroll
                for (int ci = 0; ci < 4; ci++) {
                    float v = s[nb][ci] * 0.125f;
                    if (need_mask) {
                        int row = r0 + g + (ci >> 1) * 8;
                        int key = k0 + nb * 8 + 2 * q + (ci & 1);
                        if (key > row) v = -1e30f;
                    }
                    s[nb][ci] = v;
                }

            // ---- online softmax (rows g and g+8) ----
            float mx0 = -1e30f, mx1 = -1e30f;
            #pragma unroll
            for (int nb = 0; nb < 8; nb++) {
                mx0 = fmaxf(mx0, fmaxf(s[nb][0], s[nb][1]));
                mx1 = fmaxf(mx1, fmaxf(s[nb][2], s[nb][3]));
            }
            mx0 = fmaxf(mx0, __shfl_xor_sync(0xffffffffu, mx0, 1));
            mx0 = fmaxf(mx0, __shfl_xor_sync(0xffffffffu, mx0, 2));
            mx1 = fmaxf(mx1, __shfl_xor_sync(0xffffffffu, mx1, 1));
            mx1 = fmaxf(mx1, __shfl_xor_sync(0xffffffffu, mx1, 2));
            float mn0 = fmaxf(m0r, mx0), mn1 = fmaxf(m1r, mx1);
            float a0 = __expf(m0r - mn0), a1 = __expf(m1r - mn1);
            float ls0 = 0.0f, ls1 = 0.0f;
            #pragma unroll
            for (int nb = 0; nb < 8; nb++) {
                float p0 = __expf(s[nb][0] - mn0);
                float p1 = __expf(s[nb][1] - mn0);
                float p2 = __expf(s[nb][2] - mn1);
                float p3 = __expf(s[nb][3] - mn1);
                s[nb][0] = p0; s[nb][1] = p1; s[nb][2] = p2; s[nb][3] = p3;
                ls0 += p0 + p1; ls1 += p2 + p3;
            }
            ls0 += __shfl_xor_sync(0xffffffffu, ls0, 1);
            ls0 += __shfl_xor_sync(0xffffffffu, ls0, 2);
            ls1 += __shfl_xor_sync(0xffffffffu, ls1, 1);
            ls1 += __shfl_xor_sync(0xffffffffu, ls1, 2);
            l0r = l0r * a0 + ls0; l1r = l1r * a1 + ls1;
            m0r = mn0; m1r = mn1;
            #pragma unroll
            for (int nb = 0; nb < 8; nb++) {
                o[nb][0] *= a0; o[nb][1] *= a0;
                o[nb][2] *= a1; o[nb][3] *= a1;
            }

            // ---- O += P @ V (3-pass split; P frags from S accumulators) ----
            #pragma unroll
            for (int t = 0; t < 4; t++) {
                uint32_t ph[4], pl[4];
                split2(s[2 * t][0],     s[2 * t][1],     ph[0], pl[0]);
                split2(s[2 * t][2],     s[2 * t][3],     ph[1], pl[1]);
                split2(s[2 * t + 1][0], s[2 * t + 1][1], ph[2], pl[2]);
                split2(s[2 * t + 1][2], s[2 * t + 1][3], ph[3], pl[3]);
                #pragma unroll
                for (int jp = 0; jp < 4; jp++) {
                    uint32_t vd = sVh + (uint32_t)((16 * t + (grp & 1) * 8 + (lane & 7)) * AROW
                                                   + ((jp * 2 + (grp >> 1)) * 8) * 2);
                    uint32_t vh[4], vl[4];
                    ldm_x4_t(vh, vd);
                    ldm_x4_t(vl, vd + KV_B);
                    mma16816(o[jp * 2],     ph, vh[0], vh[1]);
                    mma16816(o[jp * 2],     ph, vl[0], vl[1]);
                    mma16816(o[jp * 2],     pl, vh[0], vh[1]);
                    mma16816(o[jp * 2 + 1], ph, vh[2], vh[3]);
                    mma16816(o[jp * 2 + 1], ph, vl[2], vl[3]);
                    mma16816(o[jp * 2 + 1], pl, vh[2], vh[3]);
                }
            }
        }

        if (kt + 1 < nt) {
            asm volatile("cp.async.wait_group 0;\n" ::: "memory");
            __syncthreads();
        }
    }

    // ---- epilogue: normalize, hi/lo split, store ----
    float inv0 = 1.0f / l0r, inv1 = 1.0f / l1r;
    int row0 = q0 + w * 16 + g;
    int row1 = row0 + 8;
    #pragma unroll
    for (int nb = 0; nb < 8; nb++) {
        int c = col0 + nb * 8 + 2 * q;
        uint32_t hp, lp;
        split2(o[nb][0] * inv0, o[nb][1] * inv0, hp, lp);
        *(uint32_t*)(Ohi + (size_t)row0 * DMODEL + c) = hp;
        *(uint32_t*)(Olo + (size_t)row0 * DMODEL + c) = lp;
        split2(o[nb][2] * inv1, o[nb][3] * inv1, hp, lp);
        *(uint32_t*)(Ohi + (size_t)row1 * DMODEL + c) = hp;
        *(uint32_t*)(Olo + (size_t)row1 * DMODEL + c) = lp;
    }
}

// ---------------------------------------------------------------------------
extern "C" void kernel_launch(void* const* d_in, const int* in_sizes, int n_in,
                              void* d_out, int out_size)
{
    const float* x  = (const float*)d_in[0];
    const float* Wq = (const float*)d_in[1];
    const float* bq = (const float*)d_in[2];
    const float* Wk = (const float*)d_in[3];
    const float* bk = (const float*)d_in[4];
    const float* Wv = (const float*)d_in[5];
    const float* bv = (const float*)d_in[6];
    const float* Wo = (const float*)d_in[7];
    const float* bo = (const float*)d_in[8];
    float* out = (float*)d_out;

    __nv_bfloat16 *xhi, *xlo, *qhi, *qlo, *khi, *klo, *vhi, *vlo;
    __nv_bfloat16 *wqh, *wql, *wkh, *wkl, *wvh, *wvl, *woh, *wol;
    cudaGetSymbolAddress((void**)&xhi, g_xhi);
    cudaGetSymbolAddress((void**)&xlo, g_xlo);
    cudaGetSymbolAddress((void**)&qhi, g_qhi);
    cudaGetSymbolAddress((void**)&qlo, g_qlo);
    cudaGetSymbolAddress((void**)&khi, g_khi);
    cudaGetSymbolAddress((void**)&klo, g_klo);
    cudaGetSymbolAddress((void**)&vhi, g_vhi);
    cudaGetSymbolAddress((void**)&vlo, g_vlo);
    cudaGetSymbolAddress((void**)&wqh, g_wqhi);
    cudaGetSymbolAddress((void**)&wql, g_wqlo);
    cudaGetSymbolAddress((void**)&wkh, g_wkhi);
    cudaGetSymbolAddress((void**)&wkl, g_wklo);
    cudaGetSymbolAddress((void**)&wvh, g_wvhi);
    cudaGetSymbolAddress((void**)&wvl, g_wvlo);
    cudaGetSymbolAddress((void**)&woh, g_wohi);
    cudaGetSymbolAddress((void**)&wol, g_wolo);

    cudaFuncSetAttribute(gemm_mma_kernel,
                         cudaFuncAttributeMaxDynamicSharedMemorySize, GEMM_SMEM);
    cudaFuncSetAttribute(attn_mma_kernel,
                         cudaFuncAttributeMaxDynamicSharedMemorySize, ATTN_SMEM);

    const int NX4 = S_LEN * DMODEL / 4;
    const int NW4 = DMODEL * DMODEL / 4;

    cvt_split_kernel<<<(NX4 + 255) / 256, 256>>>(x,  xhi, xlo, NX4);
    cvt_split_kernel<<<(NW4 + 255) / 256, 256>>>(Wq, wqh, wql, NW4);
    cvt_split_kernel<<<(NW4 + 255) / 256, 256>>>(Wk, wkh, wkl, NW4);
    cvt_split_kernel<<<(NW4 + 255) / 256, 256>>>(Wv, wvh, wvl, NW4);
    cvt_split_kernel<<<(NW4 + 255) / 256, 256>>>(Wo, woh, wol, NW4);

    dim3 ggrid(DMODEL / 128, S_LEN / 128);
    gemm_mma_kernel<<<ggrid, 256, GEMM_SMEM>>>(xhi, xlo, wqh, wql, bq,
                                               nullptr, qhi, qlo, DMODEL);
    gemm_mma_kernel<<<ggrid, 256, GEMM_SMEM>>>(xhi, xlo, wkh, wkl, bk,
                                               nullptr, khi, klo, DMODEL);
    gemm_mma_kernel<<<ggrid, 256, GEMM_SMEM>>>(xhi, xlo, wvh, wvl, bv,
                                               nullptr, vhi, vlo, DMODEL);

    // attention writes its bf16 hi/lo output into xhi/xlo (x splits consumed)
    attn_mma_kernel<<<dim3(S_LEN / 128, NHEADS), 256, ATTN_SMEM>>>(
        qhi, qlo, khi, klo, vhi, vlo, xhi, xlo);

    gemm_mma_kernel<<<ggrid, 256, GEMM_SMEM>>>(xhi, xlo, woh, wol, bo,
                                               out, nullptr, nullptr, DMODEL);
}